// round 5
// baseline (speedup 1.0000x reference)
#include <cuda_runtime.h>
#include <cstdint>

// Problem constants (fixed by the dataset)
#define HOURS 168          // 24*7
#define B_SZ  32
#define N_SZ  128
#define E_SZ  64
// SU=100, SL=0, TU=1000, TL=0  ->  1/(SU-SL)=0.01, 1/(TU-TL)=0.001

#define DELTA_BLOCKS 2048                   // 2 (b,i)-rows per block
#define JOINT_BLOCKS 256                    // 65536 float4 / 256 threads

__device__ __forceinline__ float4 eval4(float ds, float dt,
                                        float4 bs, float4 cs, float4 ct)
{
    float4 r;
    r.x = fmaf(dt, ct.x, fmaf(ds, cs.x, bs.x));
    r.y = fmaf(dt, ct.y, fmaf(ds, cs.y, bs.y));
    r.z = fmaf(dt, ct.z, fmaf(ds, cs.z, bs.z));
    r.w = fmaf(dt, ct.w, fmaf(ds, cs.w, bs.w));
    return r;
}

// ---------------------------------------------------------------------------
// Fused kernel.
//  blocks [0, 2048):     delta — each block does TWO (b,i) rows of 128 j * 64 e
//  blocks [2048, 2304):  joint — 256 float4 gather-sums per block
//
// delta[b,i,j,e] = base[m][e] + ds*cs[m][e] + dt*ct[m][e]
//   m    = (i < len_b) && (j < len_b)
// Row-level uniform cases:  !vi -> m==0 everywhere;  vi && len==128 -> m==1.
// Only vi && len<128 rows need per-element selection.
// ---------------------------------------------------------------------------
__global__ __launch_bounds__(256)
void fused_kernel(const int*    __restrict__ traj,
                  const float*  __restrict__ mat,
                  const int*    __restrict__ traj_len,
                  const float4* __restrict__ emb_t,
                  const float4* __restrict__ emb_l,
                  const float4* __restrict__ emb_u,
                  const float4* __restrict__ emb_su,
                  const float4* __restrict__ emb_sl,
                  const float4* __restrict__ emb_tu,
                  const float4* __restrict__ emb_tl,
                  float4* __restrict__ out_joint,
                  float4* __restrict__ out_delta)
{
    int tid = threadIdx.x;
    int bid = blockIdx.x;

    if (bid < DELTA_BLOCKS) {
        // ----------------- delta path -----------------
        int b   = bid >> 6;                 // 64 blocks (128 rows) per batch
        int len = __ldg(&traj_len[b]);
        int e4  = tid & 15;                 // constant float4 lane
        int j0  = tid >> 4;                 // 0..15  (tid = j0*16 + e4)

        // Both mask variants of the coefficient tables, in registers.
        float4 sl0 = __ldg(&emb_sl[e4]);
        float4 sl1 = __ldg(&emb_sl[16 + e4]);
        float4 su0 = __ldg(&emb_su[e4]);
        float4 su1 = __ldg(&emb_su[16 + e4]);
        float4 tl0 = __ldg(&emb_tl[e4]);
        float4 tl1 = __ldg(&emb_tl[16 + e4]);
        float4 tu0 = __ldg(&emb_tu[e4]);
        float4 tu1 = __ldg(&emb_tu[16 + e4]);

        float4 bs0, cs0, ct0, bs1, cs1, ct1;
        bs0.x = sl0.x + tl0.x; bs0.y = sl0.y + tl0.y; bs0.z = sl0.z + tl0.z; bs0.w = sl0.w + tl0.w;
        bs1.x = sl1.x + tl1.x; bs1.y = sl1.y + tl1.y; bs1.z = sl1.z + tl1.z; bs1.w = sl1.w + tl1.w;
        cs0.x = (su0.x - sl0.x) * 0.01f;  cs0.y = (su0.y - sl0.y) * 0.01f;
        cs0.z = (su0.z - sl0.z) * 0.01f;  cs0.w = (su0.w - sl0.w) * 0.01f;
        cs1.x = (su1.x - sl1.x) * 0.01f;  cs1.y = (su1.y - sl1.y) * 0.01f;
        cs1.z = (su1.z - sl1.z) * 0.01f;  cs1.w = (su1.w - sl1.w) * 0.01f;
        ct0.x = (tu0.x - tl0.x) * 0.001f; ct0.y = (tu0.y - tl0.y) * 0.001f;
        ct0.z = (tu0.z - tl0.z) * 0.001f; ct0.w = (tu0.w - tl0.w) * 0.001f;
        ct1.x = (tu1.x - tl1.x) * 0.001f; ct1.y = (tu1.y - tl1.y) * 0.001f;
        ct1.z = (tu1.z - tl1.z) * 0.001f; ct1.w = (tu1.w - tl1.w) * 0.001f;

        #pragma unroll
        for (int rr = 0; rr < 2; rr++) {
            int bi = bid * 2 + rr;          // b*N + i  (both rows share b)
            int i  = bi & 127;
            bool vi = i < len;

            const float2* matrow = (const float2*)(mat) + (size_t)bi * N_SZ;
            float4* outrow = out_delta + (size_t)bi * (N_SZ * 16);

            // Preload all 8 mat entries: 8 LDGs in flight.
            float2 d[8];
            #pragma unroll
            for (int it = 0; it < 8; it++)
                d[it] = __ldg(&matrow[j0 + (it << 4)]);

            if (!vi) {
                // m == 0 everywhere: tight loop, no selects.
                #pragma unroll
                for (int it = 0; it < 8; it++)
                    outrow[tid + (it << 8)] = eval4(d[it].x, d[it].y, bs0, cs0, ct0);
            } else if (len == N_SZ) {
                // m == 1 everywhere.
                #pragma unroll
                for (int it = 0; it < 8; it++)
                    outrow[tid + (it << 8)] = eval4(d[it].x, d[it].y, bs1, cs1, ct1);
            } else {
                // Mixed row: per-element select on j < len.
                #pragma unroll
                for (int it = 0; it < 8; it++) {
                    int j = j0 + (it << 4);
                    bool m = j < len;
                    float4 bs, cs, ct;
                    bs.x = m ? bs1.x : bs0.x; bs.y = m ? bs1.y : bs0.y;
                    bs.z = m ? bs1.z : bs0.z; bs.w = m ? bs1.w : bs0.w;
                    cs.x = m ? cs1.x : cs0.x; cs.y = m ? cs1.y : cs0.y;
                    cs.z = m ? cs1.z : cs0.z; cs.w = m ? cs1.w : cs0.w;
                    ct.x = m ? ct1.x : ct0.x; ct.y = m ? ct1.y : ct0.y;
                    ct.z = m ? ct1.z : ct0.z; ct.w = m ? ct1.w : ct0.w;
                    outrow[tid + (it << 8)] = eval4(d[it].x, d[it].y, bs, cs, ct);
                }
            }
        }
    } else {
        // ----------------- joint path -----------------
        int gid = (bid - DELTA_BLOCKS) * 256 + tid;   // 0 .. 65535
        int row = gid >> 4;           // (b*N + n), 0..4095
        int e4  = gid & 15;

        int user = __ldg(&traj[row * 3 + 0]);
        int loc  = __ldg(&traj[row * 3 + 1]);
        int t    = __ldg(&traj[row * 3 + 2]);
        int t_idx = (t + HOURS - 1) % HOURS + 1;   // matches (t-1) % 168 + 1

        float4 a  = __ldg(&emb_t[t_idx * 16 + e4]);
        float4 bb = __ldg(&emb_l[loc   * 16 + e4]);
        float4 c  = __ldg(&emb_u[user  * 16 + e4]);

        float4 r;
        r.x = a.x + bb.x + c.x;
        r.y = a.y + bb.y + c.y;
        r.z = a.z + bb.z + c.z;
        r.w = a.w + bb.w + c.w;
        out_joint[gid] = r;
    }
}

// ---------------------------------------------------------------------------
// Launch: out = [joint (32*128*64 floats) | delta (32*128*128*64 floats)]
// ---------------------------------------------------------------------------
extern "C" void kernel_launch(void* const* d_in, const int* in_sizes, int n_in,
                              void* d_out, int out_size)
{
    const int*    traj     = (const int*)   d_in[0];
    const float*  mat      = (const float*) d_in[1];
    const int*    traj_len = (const int*)   d_in[2];
    const float4* emb_t    = (const float4*)d_in[3];
    const float4* emb_l    = (const float4*)d_in[4];
    const float4* emb_u    = (const float4*)d_in[5];
    const float4* emb_su   = (const float4*)d_in[6];
    const float4* emb_sl   = (const float4*)d_in[7];
    const float4* emb_tu   = (const float4*)d_in[8];
    const float4* emb_tl   = (const float4*)d_in[9];

    float* out = (float*)d_out;
    float4* out_joint = (float4*)out;
    float4* out_delta = (float4*)(out + (size_t)B_SZ * N_SZ * E_SZ);

    fused_kernel<<<DELTA_BLOCKS + JOINT_BLOCKS, 256>>>(
        traj, mat, traj_len,
        emb_t, emb_l, emb_u,
        emb_su, emb_sl, emb_tu, emb_tl,
        out_joint, out_delta);
}

// round 6
// speedup vs baseline: 1.1247x; 1.1247x over previous
#include <cuda_runtime.h>
#include <cstdint>

// Problem constants (fixed by the dataset)
#define HOURS 168          // 24*7
#define B_SZ  32
#define N_SZ  128
#define E_SZ  64
// SU=100, SL=0, TU=1000, TL=0  ->  1/(SU-SL)=0.01, 1/(TU-TL)=0.001

#define ROWS_PER_BLK 4
#define DELTA_BLOCKS (B_SZ * N_SZ / ROWS_PER_BLK)   // 1024
#define JOINT_BLOCKS 256                            // 65536 float4 / 256 threads

__device__ __forceinline__ float4 eval4(float ds, float dt,
                                        float4 bs, float4 cs, float4 ct)
{
    float4 r;
    r.x = fmaf(dt, ct.x, fmaf(ds, cs.x, bs.x));
    r.y = fmaf(dt, ct.y, fmaf(ds, cs.y, bs.y));
    r.z = fmaf(dt, ct.z, fmaf(ds, cs.z, bs.z));
    r.w = fmaf(dt, ct.w, fmaf(ds, cs.w, bs.w));
    return r;
}

// ---------------------------------------------------------------------------
// Fused kernel.
//  blocks [0, 1024):     delta — each block does FOUR (b,i) rows (same b) of
//                        128 j * 64 e floats each
//  blocks [1024, 1280):  joint — 256 float4 gather-sums per block
//
// delta[b,i,j,e] = base[m][e] + ds*cs[m][e] + dt*ct[m][e]
//   m = (i < len_b) && (j < len_b)
// Row-uniform cases: !vi -> m==0;  vi && len==128 -> m==1.
// e4 = tid & 15 is constant per thread -> coefficients live in registers;
// the 8-LDG table prologue is amortized over 4 rows.
// ---------------------------------------------------------------------------
__global__ __launch_bounds__(256)
void fused_kernel(const int*    __restrict__ traj,
                  const float*  __restrict__ mat,
                  const int*    __restrict__ traj_len,
                  const float4* __restrict__ emb_t,
                  const float4* __restrict__ emb_l,
                  const float4* __restrict__ emb_u,
                  const float4* __restrict__ emb_su,
                  const float4* __restrict__ emb_sl,
                  const float4* __restrict__ emb_tu,
                  const float4* __restrict__ emb_tl,
                  float4* __restrict__ out_joint,
                  float4* __restrict__ out_delta)
{
    int tid = threadIdx.x;
    int bid = blockIdx.x;

    if (bid < DELTA_BLOCKS) {
        // ----------------- delta path -----------------
        int b   = bid >> 5;                 // 32 blocks (128 rows) per batch
        int len = __ldg(&traj_len[b]);
        int e4  = tid & 15;                 // constant float4 lane
        int j0  = tid >> 4;                 // 0..15  (tid = j0*16 + e4)

        // Both mask variants of the coefficient tables, in registers.
        float4 sl0 = __ldg(&emb_sl[e4]);
        float4 sl1 = __ldg(&emb_sl[16 + e4]);
        float4 su0 = __ldg(&emb_su[e4]);
        float4 su1 = __ldg(&emb_su[16 + e4]);
        float4 tl0 = __ldg(&emb_tl[e4]);
        float4 tl1 = __ldg(&emb_tl[16 + e4]);
        float4 tu0 = __ldg(&emb_tu[e4]);
        float4 tu1 = __ldg(&emb_tu[16 + e4]);

        float4 bs0, cs0, ct0, bs1, cs1, ct1;
        bs0.x = sl0.x + tl0.x; bs0.y = sl0.y + tl0.y; bs0.z = sl0.z + tl0.z; bs0.w = sl0.w + tl0.w;
        bs1.x = sl1.x + tl1.x; bs1.y = sl1.y + tl1.y; bs1.z = sl1.z + tl1.z; bs1.w = sl1.w + tl1.w;
        cs0.x = (su0.x - sl0.x) * 0.01f;  cs0.y = (su0.y - sl0.y) * 0.01f;
        cs0.z = (su0.z - sl0.z) * 0.01f;  cs0.w = (su0.w - sl0.w) * 0.01f;
        cs1.x = (su1.x - sl1.x) * 0.01f;  cs1.y = (su1.y - sl1.y) * 0.01f;
        cs1.z = (su1.z - sl1.z) * 0.01f;  cs1.w = (su1.w - sl1.w) * 0.01f;
        ct0.x = (tu0.x - tl0.x) * 0.001f; ct0.y = (tu0.y - tl0.y) * 0.001f;
        ct0.z = (tu0.z - tl0.z) * 0.001f; ct0.w = (tu0.w - tl0.w) * 0.001f;
        ct1.x = (tu1.x - tl1.x) * 0.001f; ct1.y = (tu1.y - tl1.y) * 0.001f;
        ct1.z = (tu1.z - tl1.z) * 0.001f; ct1.w = (tu1.w - tl1.w) * 0.001f;

        #pragma unroll
        for (int rr = 0; rr < ROWS_PER_BLK; rr++) {
            int bi = bid * ROWS_PER_BLK + rr;   // b*N + i (all rows share b)
            int i  = bi & 127;
            bool vi = i < len;

            const float2* matrow = (const float2*)(mat) + (size_t)bi * N_SZ;
            float4* outrow = out_delta + (size_t)bi * (N_SZ * 16);

            // Preload all 8 mat entries: 8 LDGs in flight.
            float2 d[8];
            #pragma unroll
            for (int it = 0; it < 8; it++)
                d[it] = __ldg(&matrow[j0 + (it << 4)]);

            if (!vi) {
                // m == 0 everywhere: tight loop, no selects.
                #pragma unroll
                for (int it = 0; it < 8; it++)
                    __stcs(&outrow[tid + (it << 8)],
                           eval4(d[it].x, d[it].y, bs0, cs0, ct0));
            } else if (len == N_SZ) {
                // m == 1 everywhere.
                #pragma unroll
                for (int it = 0; it < 8; it++)
                    __stcs(&outrow[tid + (it << 8)],
                           eval4(d[it].x, d[it].y, bs1, cs1, ct1));
            } else {
                // Mixed row: per-element select on j < len.
                #pragma unroll
                for (int it = 0; it < 8; it++) {
                    int j = j0 + (it << 4);
                    bool m = j < len;
                    float4 bs, cs, ct;
                    bs.x = m ? bs1.x : bs0.x; bs.y = m ? bs1.y : bs0.y;
                    bs.z = m ? bs1.z : bs0.z; bs.w = m ? bs1.w : bs0.w;
                    cs.x = m ? cs1.x : cs0.x; cs.y = m ? cs1.y : cs0.y;
                    cs.z = m ? cs1.z : cs0.z; cs.w = m ? cs1.w : cs0.w;
                    ct.x = m ? ct1.x : ct0.x; ct.y = m ? ct1.y : ct0.y;
                    ct.z = m ? ct1.z : ct0.z; ct.w = m ? ct1.w : ct0.w;
                    __stcs(&outrow[tid + (it << 8)],
                           eval4(d[it].x, d[it].y, bs, cs, ct));
                }
            }
        }
    } else {
        // ----------------- joint path -----------------
        int gid = (bid - DELTA_BLOCKS) * 256 + tid;   // 0 .. 65535
        int row = gid >> 4;           // (b*N + n), 0..4095
        int e4  = gid & 15;

        int user = __ldg(&traj[row * 3 + 0]);
        int loc  = __ldg(&traj[row * 3 + 1]);
        int t    = __ldg(&traj[row * 3 + 2]);
        int t_idx = (t + HOURS - 1) % HOURS + 1;   // matches (t-1) % 168 + 1

        float4 a  = __ldg(&emb_t[t_idx * 16 + e4]);
        float4 bb = __ldg(&emb_l[loc   * 16 + e4]);
        float4 c  = __ldg(&emb_u[user  * 16 + e4]);

        float4 r;
        r.x = a.x + bb.x + c.x;
        r.y = a.y + bb.y + c.y;
        r.z = a.z + bb.z + c.z;
        r.w = a.w + bb.w + c.w;
        out_joint[gid] = r;
    }
}

// ---------------------------------------------------------------------------
// Launch: out = [joint (32*128*64 floats) | delta (32*128*128*64 floats)]
// ---------------------------------------------------------------------------
extern "C" void kernel_launch(void* const* d_in, const int* in_sizes, int n_in,
                              void* d_out, int out_size)
{
    const int*    traj     = (const int*)   d_in[0];
    const float*  mat      = (const float*) d_in[1];
    const int*    traj_len = (const int*)   d_in[2];
    const float4* emb_t    = (const float4*)d_in[3];
    const float4* emb_l    = (const float4*)d_in[4];
    const float4* emb_u    = (const float4*)d_in[5];
    const float4* emb_su   = (const float4*)d_in[6];
    const float4* emb_sl   = (const float4*)d_in[7];
    const float4* emb_tu   = (const float4*)d_in[8];
    const float4* emb_tl   = (const float4*)d_in[9];

    float* out = (float*)d_out;
    float4* out_joint = (float4*)out;
    float4* out_delta = (float4*)(out + (size_t)B_SZ * N_SZ * E_SZ);

    fused_kernel<<<DELTA_BLOCKS + JOINT_BLOCKS, 256>>>(
        traj, mat, traj_len,
        emb_t, emb_l, emb_u,
        emb_su, emb_sl, emb_tu, emb_tl,
        out_joint, out_delta);
}

// round 8
// speedup vs baseline: 1.1378x; 1.0117x over previous
#include <cuda_runtime.h>
#include <cstdint>

// Problem constants (fixed by the dataset)
#define HOURS 168          // 24*7
#define B_SZ  32
#define N_SZ  128
#define E_SZ  64
// SU=100, SL=0, TU=1000, TL=0  ->  1/(SU-SL)=0.01, 1/(TU-TL)=0.001

#define JOINT_BLOCKS 256                    // 65536 float4 / 256 threads
#define DELTA_BLOCKS (B_SZ * N_SZ)          // 4096, one (b,i) row per block

__device__ __forceinline__ float4 eval4(float ds, float dt,
                                        float4 bs, float4 cs, float4 ct)
{
    float4 r;
    r.x = fmaf(dt, ct.x, fmaf(ds, cs.x, bs.x));
    r.y = fmaf(dt, ct.y, fmaf(ds, cs.y, bs.y));
    r.z = fmaf(dt, ct.z, fmaf(ds, cs.z, bs.z));
    r.w = fmaf(dt, ct.w, fmaf(ds, cs.w, bs.w));
    return r;
}

// ---------------------------------------------------------------------------
// Fused kernel.
//  blocks [0, 256):      joint — 256 float4 gather-sums per block (launched
//                        first so the long-latency gathers start in wave 1)
//  blocks [256, 4352):   delta — one block per (b,i) row: 128 j * 64 e floats
//
// delta[b,i,j,e] = base[m][e] + ds*cs[m][e] + dt*ct[m][e]
//   m = (i < len_b) && (j < len_b)
// Row-uniform cases: !vi -> m==0;  vi && len==128 -> m==1.  Mixed rows select
// at the RESULT level (4 selects per float4 instead of 12).
// ---------------------------------------------------------------------------
__global__ __launch_bounds__(256)
void fused_kernel(const int*    __restrict__ traj,
                  const float*  __restrict__ mat,
                  const int*    __restrict__ traj_len,
                  const float4* __restrict__ emb_t,
                  const float4* __restrict__ emb_l,
                  const float4* __restrict__ emb_u,
                  const float4* __restrict__ emb_su,
                  const float4* __restrict__ emb_sl,
                  const float4* __restrict__ emb_tu,
                  const float4* __restrict__ emb_tl,
                  float4* __restrict__ out_joint,
                  float4* __restrict__ out_delta)
{
    int tid = threadIdx.x;
    int bid = blockIdx.x;

    if (bid >= JOINT_BLOCKS) {
        // ----------------- delta path -----------------
        int bi = bid - JOINT_BLOCKS;        // b*N + i
        int b  = bi >> 7;
        int i  = bi & 127;
        int len = __ldg(&traj_len[b]);
        bool vi = i < len;

        int e4 = tid & 15;                  // constant float4 lane
        int j0 = tid >> 4;                  // 0..15  (tid = j0*16 + e4)

        const float2* matrow = (const float2*)(mat) + (size_t)bi * N_SZ;
        float4* outrow = out_delta + (size_t)bi * (N_SZ * 16);

        // Preload all 8 mat entries: 8 LDGs in flight while tables load.
        float2 d[8];
        #pragma unroll
        for (int it = 0; it < 8; it++)
            d[it] = __ldg(&matrow[j0 + (it << 4)]);

        // Both mask variants of the coefficient tables, in registers.
        float4 sl0 = __ldg(&emb_sl[e4]);
        float4 sl1 = __ldg(&emb_sl[16 + e4]);
        float4 su0 = __ldg(&emb_su[e4]);
        float4 su1 = __ldg(&emb_su[16 + e4]);
        float4 tl0 = __ldg(&emb_tl[e4]);
        float4 tl1 = __ldg(&emb_tl[16 + e4]);
        float4 tu0 = __ldg(&emb_tu[e4]);
        float4 tu1 = __ldg(&emb_tu[16 + e4]);

        float4 bs0, cs0, ct0, bs1, cs1, ct1;
        bs0.x = sl0.x + tl0.x; bs0.y = sl0.y + tl0.y; bs0.z = sl0.z + tl0.z; bs0.w = sl0.w + tl0.w;
        bs1.x = sl1.x + tl1.x; bs1.y = sl1.y + tl1.y; bs1.z = sl1.z + tl1.z; bs1.w = sl1.w + tl1.w;
        cs0.x = (su0.x - sl0.x) * 0.01f;  cs0.y = (su0.y - sl0.y) * 0.01f;
        cs0.z = (su0.z - sl0.z) * 0.01f;  cs0.w = (su0.w - sl0.w) * 0.01f;
        cs1.x = (su1.x - sl1.x) * 0.01f;  cs1.y = (su1.y - sl1.y) * 0.01f;
        cs1.z = (su1.z - sl1.z) * 0.01f;  cs1.w = (su1.w - sl1.w) * 0.01f;
        ct0.x = (tu0.x - tl0.x) * 0.001f; ct0.y = (tu0.y - tl0.y) * 0.001f;
        ct0.z = (tu0.z - tl0.z) * 0.001f; ct0.w = (tu0.w - tl0.w) * 0.001f;
        ct1.x = (tu1.x - tl1.x) * 0.001f; ct1.y = (tu1.y - tl1.y) * 0.001f;
        ct1.z = (tu1.z - tl1.z) * 0.001f; ct1.w = (tu1.w - tl1.w) * 0.001f;

        if (!vi) {
            // m == 0 everywhere: tight loop, no selects.
            #pragma unroll
            for (int it = 0; it < 8; it++)
                __stcs(&outrow[tid + (it << 8)],
                       eval4(d[it].x, d[it].y, bs0, cs0, ct0));
        } else if (len == N_SZ) {
            // m == 1 everywhere.
            #pragma unroll
            for (int it = 0; it < 8; it++)
                __stcs(&outrow[tid + (it << 8)],
                       eval4(d[it].x, d[it].y, bs1, cs1, ct1));
        } else {
            // Mixed row: evaluate both variants, select the RESULT (4 FSELs).
            #pragma unroll
            for (int it = 0; it < 8; it++) {
                int j = j0 + (it << 4);
                bool m = j < len;
                float4 r0 = eval4(d[it].x, d[it].y, bs0, cs0, ct0);
                float4 r1 = eval4(d[it].x, d[it].y, bs1, cs1, ct1);
                float4 r;
                r.x = m ? r1.x : r0.x;
                r.y = m ? r1.y : r0.y;
                r.z = m ? r1.z : r0.z;
                r.w = m ? r1.w : r0.w;
                __stcs(&outrow[tid + (it << 8)], r);
            }
        }
    } else {
        // ----------------- joint path -----------------
        int gid = bid * 256 + tid;    // 0 .. 65535
        int row = gid >> 4;           // (b*N + n), 0..4095
        int e4  = gid & 15;

        int user = __ldg(&traj[row * 3 + 0]);
        int loc  = __ldg(&traj[row * 3 + 1]);
        int t    = __ldg(&traj[row * 3 + 2]);
        int t_idx = (t + HOURS - 1) % HOURS + 1;   // matches (t-1) % 168 + 1

        float4 a  = __ldg(&emb_t[t_idx * 16 + e4]);
        float4 bb = __ldg(&emb_l[loc   * 16 + e4]);
        float4 c  = __ldg(&emb_u[user  * 16 + e4]);

        float4 r;
        r.x = a.x + bb.x + c.x;
        r.y = a.y + bb.y + c.y;
        r.z = a.z + bb.z + c.z;
        r.w = a.w + bb.w + c.w;
        out_joint[gid] = r;
    }
}

// ---------------------------------------------------------------------------
// Launch: out = [joint (32*128*64 floats) | delta (32*128*128*64 floats)]
// ---------------------------------------------------------------------------
extern "C" void kernel_launch(void* const* d_in, const int* in_sizes, int n_in,
                              void* d_out, int out_size)
{
    const int*    traj     = (const int*)   d_in[0];
    const float*  mat      = (const float*) d_in[1];
    const int*    traj_len = (const int*)   d_in[2];
    const float4* emb_t    = (const float4*)d_in[3];
    const float4* emb_l    = (const float4*)d_in[4];
    const float4* emb_u    = (const float4*)d_in[5];
    const float4* emb_su   = (const float4*)d_in[6];
    const float4* emb_sl   = (const float4*)d_in[7];
    const float4* emb_tu   = (const float4*)d_in[8];
    const float4* emb_tl   = (const float4*)d_in[9];

    float* out = (float*)d_out;
    float4* out_joint = (float4*)out;
    float4* out_delta = (float4*)(out + (size_t)B_SZ * N_SZ * E_SZ);

    fused_kernel<<<JOINT_BLOCKS + DELTA_BLOCKS, 256>>>(
        traj, mat, traj_len,
        emb_t, emb_l, emb_u,
        emb_su, emb_sl, emb_tu, emb_tl,
        out_joint, out_delta);
}

// round 11
// speedup vs baseline: 1.1453x; 1.0065x over previous
#include <cuda_runtime.h>
#include <cstdint>

// Problem constants (fixed by the dataset)
#define HOURS 168          // 24*7
#define B_SZ  32
#define N_SZ  128
#define E_SZ  64
// SU=100, SL=0, TU=1000, TL=0  ->  1/(SU-SL)=0.01, 1/(TU-TL)=0.001

#define JOINT_BLOCKS 256                    // 65536 float4 / 256 threads
#define DELTA_BLOCKS (B_SZ * N_SZ)          // 4096, one (b,i) row per block

__device__ __forceinline__ float4 eval4(float ds, float dt,
                                        float4 bs, float4 cs, float4 ct)
{
    float4 r;
    r.x = fmaf(dt, ct.x, fmaf(ds, cs.x, bs.x));
    r.y = fmaf(dt, ct.y, fmaf(ds, cs.y, bs.y));
    r.z = fmaf(dt, ct.z, fmaf(ds, cs.z, bs.z));
    r.w = fmaf(dt, ct.w, fmaf(ds, cs.w, bs.w));
    return r;
}

// ---------------------------------------------------------------------------
// Fused kernel.
//  blocks [0, 256):     joint — 256 float4 gather-sums per block
//  blocks [256, 4352):  delta — one block per (b,i) row: 128 j * 64 e floats
//
// delta[b,i,j,e] = base[m][e] + ds*cs[m][e] + dt*ct[m][e],
//   m = (i < len_b) && (j < len_b).
// Linearity trick: r = r(m=0) + fm * (r(m=1) - r(m=0)), and the difference is
// itself eval4 of the coefficient DELTAS. One base set + one delta set lives
// in registers (24 instead of 48), mask applied as a single FMA per lane.
// __launch_bounds__(256,5) pushes occupancy to 5 CTAs/SM (40 warps).
// ---------------------------------------------------------------------------
__global__ __launch_bounds__(256, 5)
void fused_kernel(const int*    __restrict__ traj,
                  const float*  __restrict__ mat,
                  const int*    __restrict__ traj_len,
                  const float4* __restrict__ emb_t,
                  const float4* __restrict__ emb_l,
                  const float4* __restrict__ emb_u,
                  const float4* __restrict__ emb_su,
                  const float4* __restrict__ emb_sl,
                  const float4* __restrict__ emb_tu,
                  const float4* __restrict__ emb_tl,
                  float4* __restrict__ out_joint,
                  float4* __restrict__ out_delta)
{
    int tid = threadIdx.x;
    int bid = blockIdx.x;

    if (bid >= JOINT_BLOCKS) {
        // ----------------- delta path -----------------
        int bi = bid - JOINT_BLOCKS;        // b*N + i
        int b  = bi >> 7;
        int i  = bi & 127;
        int len = __ldg(&traj_len[b]);
        bool vi = i < len;

        int e4 = tid & 15;                  // constant float4 lane
        int j0 = tid >> 4;                  // 0..15  (tid = j0*16 + e4)

        const float2* matrow = (const float2*)(mat) + (size_t)bi * N_SZ;
        float4* outrow = out_delta + (size_t)bi * (N_SZ * 16);

        // Coefficient tables: base (m=0) set and delta (m=1 minus m=0) set.
        float4 sl0 = __ldg(&emb_sl[e4]);
        float4 sl1 = __ldg(&emb_sl[16 + e4]);
        float4 su0 = __ldg(&emb_su[e4]);
        float4 su1 = __ldg(&emb_su[16 + e4]);
        float4 tl0 = __ldg(&emb_tl[e4]);
        float4 tl1 = __ldg(&emb_tl[16 + e4]);
        float4 tu0 = __ldg(&emb_tu[e4]);
        float4 tu1 = __ldg(&emb_tu[16 + e4]);

        float4 bs0, cs0, ct0, dbs, dcs, dct;
        bs0.x = sl0.x + tl0.x; bs0.y = sl0.y + tl0.y;
        bs0.z = sl0.z + tl0.z; bs0.w = sl0.w + tl0.w;
        cs0.x = (su0.x - sl0.x) * 0.01f;  cs0.y = (su0.y - sl0.y) * 0.01f;
        cs0.z = (su0.z - sl0.z) * 0.01f;  cs0.w = (su0.w - sl0.w) * 0.01f;
        ct0.x = (tu0.x - tl0.x) * 0.001f; ct0.y = (tu0.y - tl0.y) * 0.001f;
        ct0.z = (tu0.z - tl0.z) * 0.001f; ct0.w = (tu0.w - tl0.w) * 0.001f;
        dbs.x = (sl1.x + tl1.x) - bs0.x; dbs.y = (sl1.y + tl1.y) - bs0.y;
        dbs.z = (sl1.z + tl1.z) - bs0.z; dbs.w = (sl1.w + tl1.w) - bs0.w;
        dcs.x = (su1.x - sl1.x) * 0.01f - cs0.x;
        dcs.y = (su1.y - sl1.y) * 0.01f - cs0.y;
        dcs.z = (su1.z - sl1.z) * 0.01f - cs0.z;
        dcs.w = (su1.w - sl1.w) * 0.01f - cs0.w;
        dct.x = (tu1.x - tl1.x) * 0.001f - ct0.x;
        dct.y = (tu1.y - tl1.y) * 0.001f - ct0.y;
        dct.z = (tu1.z - tl1.z) * 0.001f - ct0.z;
        dct.w = (tu1.w - tl1.w) * 0.001f - ct0.w;

        if (!vi) {
            // m == 0 everywhere: tight loop over two preloaded halves.
            #pragma unroll
            for (int h = 0; h < 2; h++) {
                float2 d[4];
                #pragma unroll
                for (int q = 0; q < 4; q++)
                    d[q] = __ldg(&matrow[j0 + ((h * 4 + q) << 4)]);
                #pragma unroll
                for (int q = 0; q < 4; q++) {
                    int it = h * 4 + q;
                    __stcs(&outrow[tid + (it << 8)],
                           eval4(d[q].x, d[q].y, bs0, cs0, ct0));
                }
            }
        } else {
            // Valid i: r = r0 + fm * (delta-eval), fm = (j < len).
            #pragma unroll
            for (int h = 0; h < 2; h++) {
                float2 d[4];
                #pragma unroll
                for (int q = 0; q < 4; q++)
                    d[q] = __ldg(&matrow[j0 + ((h * 4 + q) << 4)]);
                #pragma unroll
                for (int q = 0; q < 4; q++) {
                    int it = h * 4 + q;
                    int j  = j0 + (it << 4);
                    float fm = (j < len) ? 1.0f : 0.0f;
                    float4 r0 = eval4(d[q].x, d[q].y, bs0, cs0, ct0);
                    float4 df = eval4(d[q].x, d[q].y, dbs, dcs, dct);
                    float4 r;
                    r.x = fmaf(fm, df.x, r0.x);
                    r.y = fmaf(fm, df.y, r0.y);
                    r.z = fmaf(fm, df.z, r0.z);
                    r.w = fmaf(fm, df.w, r0.w);
                    __stcs(&outrow[tid + (it << 8)], r);
                }
            }
        }
    } else {
        // ----------------- joint path -----------------
        int gid = bid * 256 + tid;    // 0 .. 65535
        int row = gid >> 4;           // (b*N + n), 0..4095
        int e4  = gid & 15;

        int user = __ldg(&traj[row * 3 + 0]);
        int loc  = __ldg(&traj[row * 3 + 1]);
        int t    = __ldg(&traj[row * 3 + 2]);
        int t_idx = (t + HOURS - 1) % HOURS + 1;   // matches (t-1) % 168 + 1

        float4 a  = __ldg(&emb_t[t_idx * 16 + e4]);
        float4 bb = __ldg(&emb_l[loc   * 16 + e4]);
        float4 c  = __ldg(&emb_u[user  * 16 + e4]);

        float4 r;
        r.x = a.x + bb.x + c.x;
        r.y = a.y + bb.y + c.y;
        r.z = a.z + bb.z + c.z;
        r.w = a.w + bb.w + c.w;
        out_joint[gid] = r;
    }
}

// ---------------------------------------------------------------------------
// Launch: out = [joint (32*128*64 floats) | delta (32*128*128*64 floats)]
// ---------------------------------------------------------------------------
extern "C" void kernel_launch(void* const* d_in, const int* in_sizes, int n_in,
                              void* d_out, int out_size)
{
    const int*    traj     = (const int*)   d_in[0];
    const float*  mat      = (const float*) d_in[1];
    const int*    traj_len = (const int*)   d_in[2];
    const float4* emb_t    = (const float4*)d_in[3];
    const float4* emb_l    = (const float4*)d_in[4];
    const float4* emb_u    = (const float4*)d_in[5];
    const float4* emb_su   = (const float4*)d_in[6];
    const float4* emb_sl   = (const float4*)d_in[7];
    const float4* emb_tu   = (const float4*)d_in[8];
    const float4* emb_tl   = (const float4*)d_in[9];

    float* out = (float*)d_out;
    float4* out_joint = (float4*)out;
    float4* out_delta = (float4*)(out + (size_t)B_SZ * N_SZ * E_SZ);

    fused_kernel<<<JOINT_BLOCKS + DELTA_BLOCKS, 256>>>(
        traj, mat, traj_len,
        emb_t, emb_l, emb_u,
        emb_su, emb_sl, emb_tu, emb_tl,
        out_joint, out_delta);
}